// round 14
// baseline (speedup 1.0000x reference)
#include <cuda_runtime.h>
#include <cuda_fp16.h>
#include <cstdint>
#include <cstddef>

#define B_   2
#define T_   2048
#define C_   1024
#define NH_  16
#define HD_  64
#define C3_  3072
#define ROWS_ 4096

// ---------------------------------------------------------------------------
// Scratch (__device__ globals; allocation-free rule). All intermediates fp16.
// ---------------------------------------------------------------------------
__device__ __half g_qkv[(size_t)ROWS_ * C3_];   // 24 MB
__device__ __half g_y[(size_t)ROWS_ * C_];      //  8 MB
__device__ __half g_xh[(size_t)ROWS_ * C_];     //  8 MB  x -> half
__device__ __half g_wah[(size_t)C_ * C3_];      //  6 MB  w_attn -> half
__device__ __half g_wph[(size_t)C_ * C_];       //  2 MB  w_proj -> half

// ---------------------------------------------------------------------------
// Helpers (sm_80-era ISA only; harness ptxas target lacks the 'a' suffix)
// ---------------------------------------------------------------------------
__device__ __forceinline__ void cp_async16(void* smem_dst, const void* gsrc) {
    uint32_t s = (uint32_t)__cvta_generic_to_shared(smem_dst);
    asm volatile("cp.async.cg.shared.global [%0], [%1], 16;\n" :: "r"(s), "l"(gsrc));
}
#define CP_COMMIT asm volatile("cp.async.commit_group;\n" ::: "memory")
#define CP_WAIT_0 asm volatile("cp.async.wait_group 0;\n" ::: "memory")

// SW128 swizzle on byte offsets within a tile of 128-byte rows
#define SWZ128(off) ((off) ^ (((off) >> 3) & 0x70))

__device__ __forceinline__ void ldsm4(uint32_t r[4], uint32_t addr) {
    asm volatile("ldmatrix.sync.aligned.m8n8.x4.shared.b16 {%0,%1,%2,%3}, [%4];"
        : "=r"(r[0]), "=r"(r[1]), "=r"(r[2]), "=r"(r[3]) : "r"(addr));
}
__device__ __forceinline__ void ldsm4t(uint32_t& r0, uint32_t& r1, uint32_t& r2, uint32_t& r3,
                                       uint32_t addr) {
    asm volatile("ldmatrix.sync.aligned.m8n8.x4.trans.shared.b16 {%0,%1,%2,%3}, [%4];"
        : "=r"(r0), "=r"(r1), "=r"(r2), "=r"(r3) : "r"(addr));
}

__device__ __forceinline__ void mma_f16(float d[4], const uint32_t a[4], const uint32_t b[2]) {
    asm volatile(
        "mma.sync.aligned.m16n8k16.row.col.f32.f16.f16.f32 "
        "{%0,%1,%2,%3}, {%4,%5,%6,%7}, {%8,%9}, {%0,%1,%2,%3};\n"
        : "+f"(d[0]), "+f"(d[1]), "+f"(d[2]), "+f"(d[3])
        : "r"(a[0]), "r"(a[1]), "r"(a[2]), "r"(a[3]), "r"(b[0]), "r"(b[1]));
}

__device__ __forceinline__ float ex2f(float x) {
    float y;
    asm("ex2.approx.ftz.f32 %0, %1;" : "=f"(y) : "f"(x));
    return y;
}

// pack two floats to f16x2: lo -> low half, hi -> high half
__device__ __forceinline__ uint32_t pack_h2(float lo, float hi) {
    uint32_t u;
    asm("cvt.rn.f16x2.f32 %0, %1, %2;" : "=r"(u) : "f"(hi), "f"(lo));
    return u;
}

// ---------------------------------------------------------------------------
// Fused fp32 -> fp16 convert for x, w_attn, w_proj in one launch
// ---------------------------------------------------------------------------
__global__ void convert_all_kernel(const float4* __restrict__ x,  uint2* __restrict__ xh,
                                   const float4* __restrict__ wa, uint2* __restrict__ wah,
                                   const float4* __restrict__ wp, uint2* __restrict__ wph,
                                   int n4x, int n4a, int n4p)
{
    int i = blockIdx.x * 256 + threadIdx.x;
    const float4* src;
    uint2* dst;
    int j;
    if (i < n4x)            { src = x;  dst = xh;  j = i; }
    else if (i < n4x + n4a) { src = wa; dst = wah; j = i - n4x; }
    else if (i < n4x + n4a + n4p) { src = wp; dst = wph; j = i - n4x - n4a; }
    else return;
    float4 v = src[j];
    __half2 a = __floats2half2_rn(v.x, v.y);
    __half2 b = __floats2half2_rn(v.z, v.w);
    dst[j] = make_uint2(*(uint32_t*)&a, *(uint32_t*)&b);
}

// ---------------------------------------------------------------------------
// fp16 GEMM — EXACT R8/R13 pipeline (best measured):
// block 128x128x64, 128 threads, warp grid 2x2, warp tile 64x64,
// 2-stage cp.async, load issued at top of iter, wait+sync after compute.
// ---------------------------------------------------------------------------
#define BM 128
#define BN 128
#define BK 64
#define A_ST_BYTES (BM * 128)
#define B_ST_BYTES (BK * 256)
#define STG_BYTES (A_ST_BYTES + B_ST_BYTES)   // 32768
#define GEMM_SMEM (2 * STG_BYTES)             // 65536

template<bool OUT_HALF>
__global__ __launch_bounds__(128, 2)
void gemm_f16(const __half* __restrict__ A, const __half* __restrict__ Bm,
              void* __restrict__ Cv, int M, int N, int K)
{
    extern __shared__ char smc[];
    const uint32_t sbase = (uint32_t)__cvta_generic_to_shared(smc);
    const int tid  = threadIdx.x;
    const int lane = tid & 31;
    const int warp = tid >> 5;        // 0..3
    const int wm   = warp & 1;
    const int wn   = warp >> 1;
    const int g    = lane >> 2;
    const int tg   = lane & 3;
    const int bm   = blockIdx.y * BM;
    const int bn   = blockIdx.x * BN;

    float acc[4][8][4];
    #pragma unroll
    for (int i = 0; i < 4; i++)
        #pragma unroll
        for (int j = 0; j < 8; j++)
            #pragma unroll
            for (int k = 0; k < 4; k++) acc[i][j][k] = 0.f;

    auto load_stage = [&](int kt, int s) {
        char* As = smc + s * STG_BYTES;
        char* Bs = As + A_ST_BYTES;
        #pragma unroll
        for (int p = 0; p < 8; p++) {        // A: 128 rows x 8 chunks of 16B
            int idx = tid + p * 128;
            int r = idx >> 3, c = idx & 7;
            cp_async16(As + SWZ128(r * 128 + c * 16),
                       A + (size_t)(bm + r) * K + kt * BK + c * 8);
        }
        #pragma unroll
        for (int p = 0; p < 8; p++) {        // B: 64 rows x 16 chunks (256B rows)
            int idx = tid + p * 128;
            int r = idx >> 4, c = idx & 15;
            cp_async16(Bs + r * 256 + ((c ^ (r & 7)) * 16),
                       Bm + (size_t)(kt * BK + r) * N + bn + c * 8);
        }
    };

    const int nk = K / BK;
    load_stage(0, 0); CP_COMMIT;
    CP_WAIT_0; __syncthreads();

    for (int kt = 0; kt < nk; kt++) {
        const int cur = kt & 1;
        if (kt + 1 < nk) { load_stage(kt + 1, cur ^ 1); CP_COMMIT; }

        const uint32_t aS = sbase + cur * STG_BYTES;
        const uint32_t bS = aS + A_ST_BYTES;

        #pragma unroll
        for (int ks = 0; ks < 4; ks++) {
            uint32_t af[4][4];
            #pragma unroll
            for (int mt = 0; mt < 4; mt++) {
                const int row = wm * 64 + mt * 16 + (lane & 15);
                const int ch  = ks * 2 + (lane >> 4);
                ldsm4(af[mt], aS + SWZ128(row * 128 + ch * 16));
            }
            uint32_t bf[8][2];
            #pragma unroll
            for (int pr = 0; pr < 4; pr++) {
                const int row = ks * 16 + (lane & 7) + (lane & 8);
                const int ch  = wn * 8 + pr * 2 + (lane >> 4);
                uint32_t r0, r1, r2, r3;
                ldsm4t(r0, r1, r2, r3, bS + row * 256 + ((ch ^ (row & 7)) * 16));
                bf[pr * 2][0] = r0;     bf[pr * 2][1] = r1;
                bf[pr * 2 + 1][0] = r2; bf[pr * 2 + 1][1] = r3;
            }
            #pragma unroll
            for (int mt = 0; mt < 4; mt++)
                #pragma unroll
                for (int nt = 0; nt < 8; nt++)
                    mma_f16(acc[mt][nt], af[mt], bf[nt]);
        }

        if (kt + 1 < nk) { CP_WAIT_0; __syncthreads(); }
    }

    // Epilogue: c0,c1 -> (row g, cols 2tg,2tg+1); c2,c3 -> row g+8
    #pragma unroll
    for (int mt = 0; mt < 4; mt++) {
        const int r0 = bm + wm * 64 + mt * 16 + g;
        #pragma unroll
        for (int nt = 0; nt < 8; nt++) {
            const int cc = bn + wn * 64 + nt * 8 + 2 * tg;
            if (OUT_HALF) {
                __half* Ch = (__half*)Cv;
                *(__half2*)&Ch[(size_t)r0 * N + cc]       = __floats2half2_rn(acc[mt][nt][0], acc[mt][nt][1]);
                *(__half2*)&Ch[(size_t)(r0 + 8) * N + cc] = __floats2half2_rn(acc[mt][nt][2], acc[mt][nt][3]);
            } else {
                float* Cf = (float*)Cv;
                *(float2*)&Cf[(size_t)r0 * N + cc]       = make_float2(acc[mt][nt][0], acc[mt][nt][1]);
                *(float2*)&Cf[(size_t)(r0 + 8) * N + cc] = make_float2(acc[mt][nt][2], acc[mt][nt][3]);
            }
        }
    }
}

// ---------------------------------------------------------------------------
// Flash attention — R10/R13 config (q64/KV128, 128 thr, 2 CTAs/SM) with the
// causal LAST TILE PEELED: main kv-loop is mask-free; the tail tile runs a
// width-templated body (NT=8 for even qt -> half the MMAs/softmax; NT=16 for
// odd qt) and a trimmed 64-row KV load when the smem slot is pre-initialized.
// Math is bit-identical to the masked full-width version.
// smem: Q[0,8K) K[8K,40K) x2(16K) V[40K,72K) x2(16K) = 73728 B.
// ---------------------------------------------------------------------------
#define Q_OFF 0
#define K_OFF 8192
#define V_OFF 40960
#define KV_STG 16384
#define ATT_SMEM 73728

struct NTag8  { static constexpr int value = 8;  };
struct NTag16 { static constexpr int value = 16; };

__global__ __launch_bounds__(128, 2)
void attn_kernel(const __half* __restrict__ qkv, __half* __restrict__ y)
{
    extern __shared__ char smc[];
    const uint32_t sbase = (uint32_t)__cvta_generic_to_shared(smc);
    const int tid  = threadIdx.x;
    const int lane = tid & 31;
    const int warp = tid >> 5;        // 0..3
    const int g    = lane >> 2;
    const int tg   = lane & 3;

    const int qt = gridDim.x - 1 - blockIdx.x;   // heavy tiles first (0..31)
    const int bh = blockIdx.y;
    const int b  = bh >> 4;
    const int h  = bh & 15;

    const __half* base = qkv + (size_t)b * T_ * C3_;
    const int qcol = h * HD_;
    const int kcol = C_ + h * HD_;
    const int vcol = 2 * C_ + h * HD_;

    // Q tile 64x64 halves -> smem (swizzled), once
    #pragma unroll
    for (int p = 0; p < 4; p++) {
        int idx = tid + p * 128;
        int r = idx >> 3, c = idx & 7;
        cp_async16(smc + Q_OFF + SWZ128(r * 128 + c * 16),
                   base + (size_t)(qt * 64 + r) * C3_ + qcol + c * 8);
    }

    // rows8: number of 16-row chunks to load (8 = full 128 rows, 4 = 64 rows)
    auto load_kv = [&](int j, int s, int rows8) {
        for (int p = 0; p < rows8; p++) {
            int idx = tid + p * 128;
            int r = idx >> 3, c = idx & 7;
            const size_t grow = (size_t)(j * 128 + r) * C3_;
            const int so = SWZ128(r * 128 + c * 16);
            cp_async16(smc + K_OFF + s * KV_STG + so, base + grow + kcol + c * 8);
            cp_async16(smc + V_OFF + s * KV_STG + so, base + grow + vcol + c * 8);
        }
    };

    const int kvneed    = qt * 64 + 64;
    const int jend      = (kvneed - 1) >> 7;          // last kv-128 tile index
    const bool half_last = (kvneed & 127) != 0;       // even qt -> 64-wide tail

    load_kv(0, 0, 8); CP_COMMIT;
    CP_WAIT_0; __syncthreads();

    // Q a-frags, held in registers for the whole kv loop
    uint32_t qf[4][4];
    #pragma unroll
    for (int ks = 0; ks < 4; ks++) {
        const int row = warp * 16 + (lane & 15);
        const int ch  = ks * 2 + (lane >> 4);
        ldsm4(qf[ks], sbase + Q_OFF + SWZ128(row * 128 + ch * 16));
    }

    float o[8][4];
    #pragma unroll
    for (int i = 0; i < 8; i++)
        #pragma unroll
        for (int jj = 0; jj < 4; jj++) o[i][jj] = 0.f;
    float m0 = -INFINITY, m1 = -INFINITY, l0 = 0.f, l1 = 0.f;

    const float SC = 0.125f * 1.4426950408889634f;   // 1/sqrt(64) * log2(e)

    // Tile body: NT = kv columns / 8 (8 or 16), optional causal mask at tile j.
    auto do_tile = [&](int j, uint32_t kS, uint32_t vS, auto ntag, bool domask) {
        constexpr int NT  = decltype(ntag)::value;
        constexpr int KS2 = NT / 2;

        // S = Q @ K^T
        float s[NT][4];
        #pragma unroll
        for (int nt = 0; nt < NT; nt++)
            #pragma unroll
            for (int k4 = 0; k4 < 4; k4++) s[nt][k4] = 0.f;

        #pragma unroll
        for (int ks = 0; ks < 4; ks++) {
            uint32_t bf[NT][2];
            #pragma unroll
            for (int pr = 0; pr < KS2; pr++) {
                const int row = pr * 16 + (lane & 7) + ((lane >> 4) << 3);
                const int ch  = ks * 2 + ((lane >> 3) & 1);
                uint32_t rr[4];
                ldsm4(rr, kS + SWZ128(row * 128 + ch * 16));
                bf[pr * 2][0] = rr[0];     bf[pr * 2][1] = rr[1];
                bf[pr * 2 + 1][0] = rr[2]; bf[pr * 2 + 1][1] = rr[3];
            }
            #pragma unroll
            for (int nt = 0; nt < NT; nt++)
                mma_f16(s[nt], qf[ks], bf[nt]);
        }

        // scale
        #pragma unroll
        for (int nt = 0; nt < NT; nt++) {
            s[nt][0] *= SC; s[nt][1] *= SC; s[nt][2] *= SC; s[nt][3] *= SC;
        }

        // causal mask (tail tile only)
        if (domask) {
            const int rg0 = qt * 64 + warp * 16 + g;
            const int rg1 = rg0 + 8;
            #pragma unroll
            for (int nt = 0; nt < NT; nt++) {
                const int c0 = j * 128 + nt * 8 + 2 * tg;
                if (c0     > rg0) s[nt][0] = -1e30f;
                if (c0 + 1 > rg0) s[nt][1] = -1e30f;
                if (c0     > rg1) s[nt][2] = -1e30f;
                if (c0 + 1 > rg1) s[nt][3] = -1e30f;
            }
        }

        // online softmax, base-2 (row g -> s[.][0,1]; row g+8 -> s[.][2,3])
        float mt0 = -INFINITY, mt1 = -INFINITY;
        #pragma unroll
        for (int nt = 0; nt < NT; nt++) {
            mt0 = fmaxf(mt0, fmaxf(s[nt][0], s[nt][1]));
            mt1 = fmaxf(mt1, fmaxf(s[nt][2], s[nt][3]));
        }
        mt0 = fmaxf(mt0, __shfl_xor_sync(0xffffffffu, mt0, 1));
        mt0 = fmaxf(mt0, __shfl_xor_sync(0xffffffffu, mt0, 2));
        mt1 = fmaxf(mt1, __shfl_xor_sync(0xffffffffu, mt1, 1));
        mt1 = fmaxf(mt1, __shfl_xor_sync(0xffffffffu, mt1, 2));

        const float mn0 = fmaxf(m0, mt0), mn1 = fmaxf(m1, mt1);
        const float f0 = ex2f(m0 - mn0), f1 = ex2f(m1 - mn1);

        // exp + pack P directly into a-frags (c-frag layout == a-frag layout)
        uint32_t pf[KS2][4];
        float ls0 = 0.f, ls1 = 0.f;
        #pragma unroll
        for (int ks = 0; ks < KS2; ks++) {
            const float pa0 = ex2f(s[2*ks][0] - mn0);
            const float pa1 = ex2f(s[2*ks][1] - mn0);
            const float pa2 = ex2f(s[2*ks][2] - mn1);
            const float pa3 = ex2f(s[2*ks][3] - mn1);
            const float pb0 = ex2f(s[2*ks+1][0] - mn0);
            const float pb1 = ex2f(s[2*ks+1][1] - mn0);
            const float pb2 = ex2f(s[2*ks+1][2] - mn1);
            const float pb3 = ex2f(s[2*ks+1][3] - mn1);
            ls0 += pa0 + pa1 + pb0 + pb1;
            ls1 += pa2 + pa3 + pb2 + pb3;
            pf[ks][0] = pack_h2(pa0, pa1);
            pf[ks][1] = pack_h2(pa2, pa3);
            pf[ks][2] = pack_h2(pb0, pb1);
            pf[ks][3] = pack_h2(pb2, pb3);
        }
        ls0 += __shfl_xor_sync(0xffffffffu, ls0, 1);
        ls0 += __shfl_xor_sync(0xffffffffu, ls0, 2);
        ls1 += __shfl_xor_sync(0xffffffffu, ls1, 1);
        ls1 += __shfl_xor_sync(0xffffffffu, ls1, 2);

        l0 = l0 * f0 + ls0;
        l1 = l1 * f1 + ls1;
        m0 = mn0; m1 = mn1;

        #pragma unroll
        for (int nt = 0; nt < 8; nt++) {
            o[nt][0] *= f0; o[nt][1] *= f0;
            o[nt][2] *= f1; o[nt][3] *= f1;
        }

        // O += P @ V   (P a-frags in registers; V b-frags via ldmatrix.trans)
        #pragma unroll
        for (int ks = 0; ks < KS2; ks++) {
            uint32_t bf[8][2];
            #pragma unroll
            for (int pr = 0; pr < 4; pr++) {
                const int row = ks * 16 + (lane & 15);
                const int ch  = pr * 2 + (lane >> 4);
                uint32_t r0, r1, r2, r3;
                ldsm4t(r0, r1, r2, r3, vS + SWZ128(row * 128 + ch * 16));
                bf[pr * 2][0] = r0;     bf[pr * 2][1] = r1;
                bf[pr * 2 + 1][0] = r2; bf[pr * 2 + 1][1] = r3;
            }
            #pragma unroll
            for (int nt = 0; nt < 8; nt++)
                mma_f16(o[nt], pf[ks], bf[nt]);
        }
    };

    // Main loop: mask-free full-width tiles for j < jend
    for (int j = 0; j < jend; j++) {
        const int nxt = j + 1;
        // Trim the tail-tile load to 64 rows only when its smem slot was
        // already filled with finite data (slot reused from tile nxt-2).
        const int rows8 = (half_last && nxt == jend && jend >= 2) ? 4 : 8;
        load_kv(nxt, nxt & 1, rows8); CP_COMMIT;

        const uint32_t kS = sbase + K_OFF + (j & 1) * KV_STG;
        const uint32_t vS = sbase + V_OFF + (j & 1) * KV_STG;
        do_tile(j, kS, vS, NTag16{}, false);

        CP_WAIT_0; __syncthreads();
    }

    // Tail tile j = jend: masked; half-width when even qt
    {
        const uint32_t kS = sbase + K_OFF + (jend & 1) * KV_STG;
        const uint32_t vS = sbase + V_OFF + (jend & 1) * KV_STG;
        if (half_last) do_tile(jend, kS, vS, NTag8{},  true);
        else           do_tile(jend, kS, vS, NTag16{}, true);
    }

    // normalize + write y (half)
    const float i0 = 1.f / l0, i1 = 1.f / l1;
    const int r0 = b * T_ + qt * 64 + warp * 16 + g;
    #pragma unroll
    for (int nt = 0; nt < 8; nt++) {
        const int c = h * HD_ + nt * 8 + 2 * tg;
        *(__half2*)&y[(size_t)r0 * C_ + c] =
            __floats2half2_rn(o[nt][0] * i0, o[nt][1] * i0);
        *(__half2*)&y[(size_t)(r0 + 8) * C_ + c] =
            __floats2half2_rn(o[nt][2] * i1, o[nt][3] * i1);
    }
}

// ---------------------------------------------------------------------------
// Launch chain: convert -> qkv GEMM -> attention -> proj GEMM
// ---------------------------------------------------------------------------
extern "C" void kernel_launch(void* const* d_in, const int* in_sizes, int n_in,
                              void* d_out, int out_size)
{
    (void)in_sizes; (void)n_in; (void)out_size;
    const float* x      = (const float*)d_in[0];
    const float* w_attn = (const float*)d_in[1];
    const float* w_proj = (const float*)d_in[2];
    float* out = (float*)d_out;

    __half *qkv, *y, *xh, *wah, *wph;
    cudaGetSymbolAddress((void**)&qkv, g_qkv);
    cudaGetSymbolAddress((void**)&y,   g_y);
    cudaGetSymbolAddress((void**)&xh,  g_xh);
    cudaGetSymbolAddress((void**)&wah, g_wah);
    cudaGetSymbolAddress((void**)&wph, g_wph);

    cudaFuncSetAttribute(gemm_f16<true>,  cudaFuncAttributeMaxDynamicSharedMemorySize, GEMM_SMEM);
    cudaFuncSetAttribute(gemm_f16<false>, cudaFuncAttributeMaxDynamicSharedMemorySize, GEMM_SMEM);
    cudaFuncSetAttribute(attn_kernel,     cudaFuncAttributeMaxDynamicSharedMemorySize, ATT_SMEM);

    const int n4x = ROWS_ * C_ / 4;       // 1048576
    const int n4a = C_ * C3_ / 4;         // 786432
    const int n4p = C_ * C_ / 4;          // 262144
    const int n4  = n4x + n4a + n4p;
    convert_all_kernel<<<(n4 + 255) / 256, 256>>>(
        (const float4*)x, (uint2*)xh,
        (const float4*)w_attn, (uint2*)wah,
        (const float4*)w_proj, (uint2*)wph,
        n4x, n4a, n4p);

    gemm_f16<true><<<dim3(C3_ / BN, ROWS_ / BM), 128, GEMM_SMEM>>>(xh, wah, qkv, ROWS_, C3_, C_);
    attn_kernel<<<dim3(T_ / 64, B_ * NH_), 128, ATT_SMEM>>>(qkv, y);
    gemm_f16<false><<<dim3(C_ / BN, ROWS_ / BM), 128, GEMM_SMEM>>>(y, wph, out, ROWS_, C_, C_);
}

// round 15
// speedup vs baseline: 1.0145x; 1.0145x over previous
#include <cuda_runtime.h>
#include <cuda_fp16.h>
#include <cstdint>
#include <cstddef>

#define B_   2
#define T_   2048
#define C_   1024
#define NH_  16
#define HD_  64
#define C3_  3072
#define ROWS_ 4096

// ---------------------------------------------------------------------------
// Scratch (__device__ globals; allocation-free rule). All intermediates fp16.
// ---------------------------------------------------------------------------
__device__ __half g_qkv[(size_t)ROWS_ * C3_];   // 24 MB
__device__ __half g_y[(size_t)ROWS_ * C_];      //  8 MB
__device__ __half g_xh[(size_t)ROWS_ * C_];     //  8 MB  x -> half
__device__ __half g_wah[(size_t)C_ * C3_];      //  6 MB  w_attn -> half
__device__ __half g_wph[(size_t)C_ * C_];       //  2 MB  w_proj -> half

// ---------------------------------------------------------------------------
// Helpers (sm_80-era ISA only; harness ptxas target lacks the 'a' suffix)
// ---------------------------------------------------------------------------
__device__ __forceinline__ void cp_async16(void* smem_dst, const void* gsrc) {
    uint32_t s = (uint32_t)__cvta_generic_to_shared(smem_dst);
    asm volatile("cp.async.cg.shared.global [%0], [%1], 16;\n" :: "r"(s), "l"(gsrc));
}
#define CP_COMMIT asm volatile("cp.async.commit_group;\n" ::: "memory")
#define CP_WAIT_0 asm volatile("cp.async.wait_group 0;\n" ::: "memory")

// SW128 swizzle on byte offsets within a tile of 128-byte rows
#define SWZ128(off) ((off) ^ (((off) >> 3) & 0x70))

__device__ __forceinline__ void ldsm4(uint32_t r[4], uint32_t addr) {
    asm volatile("ldmatrix.sync.aligned.m8n8.x4.shared.b16 {%0,%1,%2,%3}, [%4];"
        : "=r"(r[0]), "=r"(r[1]), "=r"(r[2]), "=r"(r[3]) : "r"(addr));
}
__device__ __forceinline__ void ldsm4t(uint32_t& r0, uint32_t& r1, uint32_t& r2, uint32_t& r3,
                                       uint32_t addr) {
    asm volatile("ldmatrix.sync.aligned.m8n8.x4.trans.shared.b16 {%0,%1,%2,%3}, [%4];"
        : "=r"(r0), "=r"(r1), "=r"(r2), "=r"(r3) : "r"(addr));
}

__device__ __forceinline__ void mma_f16(float d[4], const uint32_t a[4], const uint32_t b[2]) {
    asm volatile(
        "mma.sync.aligned.m16n8k16.row.col.f32.f16.f16.f32 "
        "{%0,%1,%2,%3}, {%4,%5,%6,%7}, {%8,%9}, {%0,%1,%2,%3};\n"
        : "+f"(d[0]), "+f"(d[1]), "+f"(d[2]), "+f"(d[3])
        : "r"(a[0]), "r"(a[1]), "r"(a[2]), "r"(a[3]), "r"(b[0]), "r"(b[1]));
}

__device__ __forceinline__ float ex2f(float x) {
    float y;
    asm("ex2.approx.ftz.f32 %0, %1;" : "=f"(y) : "f"(x));
    return y;
}

// pack two floats to f16x2: lo -> low half, hi -> high half
__device__ __forceinline__ uint32_t pack_h2(float lo, float hi) {
    uint32_t u;
    asm("cvt.rn.f16x2.f32 %0, %1, %2;" : "=r"(u) : "f"(hi), "f"(lo));
    return u;
}

// packed fp16x2 multiply
__device__ __forceinline__ uint32_t mul_h2(uint32_t a, uint32_t b) {
    uint32_t r;
    asm("mul.f16x2 %0, %1, %2;" : "=r"(r) : "r"(a), "r"(b));
    return r;
}

// ---------------------------------------------------------------------------
// Fused fp32 -> fp16 convert for x, w_attn, w_proj in one launch
// ---------------------------------------------------------------------------
__global__ void convert_all_kernel(const float4* __restrict__ x,  uint2* __restrict__ xh,
                                   const float4* __restrict__ wa, uint2* __restrict__ wah,
                                   const float4* __restrict__ wp, uint2* __restrict__ wph,
                                   int n4x, int n4a, int n4p)
{
    int i = blockIdx.x * 256 + threadIdx.x;
    const float4* src;
    uint2* dst;
    int j;
    if (i < n4x)            { src = x;  dst = xh;  j = i; }
    else if (i < n4x + n4a) { src = wa; dst = wah; j = i - n4x; }
    else if (i < n4x + n4a + n4p) { src = wp; dst = wph; j = i - n4x - n4a; }
    else return;
    float4 v = src[j];
    __half2 a = __floats2half2_rn(v.x, v.y);
    __half2 b = __floats2half2_rn(v.z, v.w);
    dst[j] = make_uint2(*(uint32_t*)&a, *(uint32_t*)&b);
}

// ---------------------------------------------------------------------------
// fp16 GEMM — EXACT R8/R13 pipeline (best measured):
// block 128x128x64, 128 threads, warp grid 2x2, warp tile 64x64,
// 2-stage cp.async, load issued at top of iter, wait+sync after compute.
// ---------------------------------------------------------------------------
#define BM 128
#define BN 128
#define BK 64
#define A_ST_BYTES (BM * 128)
#define B_ST_BYTES (BK * 256)
#define STG_BYTES (A_ST_BYTES + B_ST_BYTES)   // 32768
#define GEMM_SMEM (2 * STG_BYTES)             // 65536

template<bool OUT_HALF>
__global__ __launch_bounds__(128, 2)
void gemm_f16(const __half* __restrict__ A, const __half* __restrict__ Bm,
              void* __restrict__ Cv, int M, int N, int K)
{
    extern __shared__ char smc[];
    const uint32_t sbase = (uint32_t)__cvta_generic_to_shared(smc);
    const int tid  = threadIdx.x;
    const int lane = tid & 31;
    const int warp = tid >> 5;        // 0..3
    const int wm   = warp & 1;
    const int wn   = warp >> 1;
    const int g    = lane >> 2;
    const int tg   = lane & 3;
    const int bm   = blockIdx.y * BM;
    const int bn   = blockIdx.x * BN;

    float acc[4][8][4];
    #pragma unroll
    for (int i = 0; i < 4; i++)
        #pragma unroll
        for (int j = 0; j < 8; j++)
            #pragma unroll
            for (int k = 0; k < 4; k++) acc[i][j][k] = 0.f;

    auto load_stage = [&](int kt, int s) {
        char* As = smc + s * STG_BYTES;
        char* Bs = As + A_ST_BYTES;
        #pragma unroll
        for (int p = 0; p < 8; p++) {        // A: 128 rows x 8 chunks of 16B
            int idx = tid + p * 128;
            int r = idx >> 3, c = idx & 7;
            cp_async16(As + SWZ128(r * 128 + c * 16),
                       A + (size_t)(bm + r) * K + kt * BK + c * 8);
        }
        #pragma unroll
        for (int p = 0; p < 8; p++) {        // B: 64 rows x 16 chunks (256B rows)
            int idx = tid + p * 128;
            int r = idx >> 4, c = idx & 15;
            cp_async16(Bs + r * 256 + ((c ^ (r & 7)) * 16),
                       Bm + (size_t)(kt * BK + r) * N + bn + c * 8);
        }
    };

    const int nk = K / BK;
    load_stage(0, 0); CP_COMMIT;
    CP_WAIT_0; __syncthreads();

    for (int kt = 0; kt < nk; kt++) {
        const int cur = kt & 1;
        if (kt + 1 < nk) { load_stage(kt + 1, cur ^ 1); CP_COMMIT; }

        const uint32_t aS = sbase + cur * STG_BYTES;
        const uint32_t bS = aS + A_ST_BYTES;

        #pragma unroll
        for (int ks = 0; ks < 4; ks++) {
            uint32_t af[4][4];
            #pragma unroll
            for (int mt = 0; mt < 4; mt++) {
                const int row = wm * 64 + mt * 16 + (lane & 15);
                const int ch  = ks * 2 + (lane >> 4);
                ldsm4(af[mt], aS + SWZ128(row * 128 + ch * 16));
            }
            uint32_t bf[8][2];
            #pragma unroll
            for (int pr = 0; pr < 4; pr++) {
                const int row = ks * 16 + (lane & 7) + (lane & 8);
                const int ch  = wn * 8 + pr * 2 + (lane >> 4);
                uint32_t r0, r1, r2, r3;
                ldsm4t(r0, r1, r2, r3, bS + row * 256 + ((ch ^ (row & 7)) * 16));
                bf[pr * 2][0] = r0;     bf[pr * 2][1] = r1;
                bf[pr * 2 + 1][0] = r2; bf[pr * 2 + 1][1] = r3;
            }
            #pragma unroll
            for (int mt = 0; mt < 4; mt++)
                #pragma unroll
                for (int nt = 0; nt < 8; nt++)
                    mma_f16(acc[mt][nt], af[mt], bf[nt]);
        }

        if (kt + 1 < nk) { CP_WAIT_0; __syncthreads(); }
    }

    // Epilogue: c0,c1 -> (row g, cols 2tg,2tg+1); c2,c3 -> row g+8
    #pragma unroll
    for (int mt = 0; mt < 4; mt++) {
        const int r0 = bm + wm * 64 + mt * 16 + g;
        #pragma unroll
        for (int nt = 0; nt < 8; nt++) {
            const int cc = bn + wn * 64 + nt * 8 + 2 * tg;
            if (OUT_HALF) {
                __half* Ch = (__half*)Cv;
                *(__half2*)&Ch[(size_t)r0 * N + cc]       = __floats2half2_rn(acc[mt][nt][0], acc[mt][nt][1]);
                *(__half2*)&Ch[(size_t)(r0 + 8) * N + cc] = __floats2half2_rn(acc[mt][nt][2], acc[mt][nt][3]);
            } else {
                float* Cf = (float*)Cv;
                *(float2*)&Cf[(size_t)r0 * N + cc]       = make_float2(acc[mt][nt][0], acc[mt][nt][1]);
                *(float2*)&Cf[(size_t)(r0 + 8) * N + cc] = make_float2(acc[mt][nt][2], acc[mt][nt][3]);
            }
        }
    }
}

// ---------------------------------------------------------------------------
// Flash attention — EXACT R13 structure (q64/KV128, 128 thr, 2 CTAs/SM),
// with ONE change: the softmax scale (1/sqrt(HD) * log2e) is pre-folded into
// the Q fragments ONCE per block via mul.f16x2 (16 ops/warp), replacing the
// 64-FMUL-per-tile `s *= SC` loop. One extra fp16 rounding on Q (~2^-11).
// smem: Q[0,8K) K[8K,40K) x2(16K) V[40K,72K) x2(16K) = 73728 B.
// ---------------------------------------------------------------------------
#define Q_OFF 0
#define K_OFF 8192
#define V_OFF 40960
#define KV_STG 16384
#define ATT_SMEM 73728

__global__ __launch_bounds__(128, 2)
void attn_kernel(const __half* __restrict__ qkv, __half* __restrict__ y)
{
    extern __shared__ char smc[];
    const uint32_t sbase = (uint32_t)__cvta_generic_to_shared(smc);
    const int tid  = threadIdx.x;
    const int lane = tid & 31;
    const int warp = tid >> 5;        // 0..3
    const int g    = lane >> 2;
    const int tg   = lane & 3;

    const int qt = gridDim.x - 1 - blockIdx.x;   // heavy tiles first (0..31)
    const int bh = blockIdx.y;
    const int b  = bh >> 4;
    const int h  = bh & 15;

    const __half* base = qkv + (size_t)b * T_ * C3_;
    const int qcol = h * HD_;
    const int kcol = C_ + h * HD_;
    const int vcol = 2 * C_ + h * HD_;

    // Q tile 64x64 halves -> smem (swizzled), once
    #pragma unroll
    for (int p = 0; p < 4; p++) {
        int idx = tid + p * 128;
        int r = idx >> 3, c = idx & 7;
        cp_async16(smc + Q_OFF + SWZ128(r * 128 + c * 16),
                   base + (size_t)(qt * 64 + r) * C3_ + qcol + c * 8);
    }

    auto load_kv = [&](int j, int s) {
        #pragma unroll
        for (int p = 0; p < 8; p++) {          // 128 rows x 8 chunks each
            int idx = tid + p * 128;
            int r = idx >> 3, c = idx & 7;
            const size_t grow = (size_t)(j * 128 + r) * C3_;
            const int so = SWZ128(r * 128 + c * 16);
            cp_async16(smc + K_OFF + s * KV_STG + so, base + grow + kcol + c * 8);
            cp_async16(smc + V_OFF + s * KV_STG + so, base + grow + vcol + c * 8);
        }
    };

    load_kv(0, 0); CP_COMMIT;
    CP_WAIT_0; __syncthreads();

    // Q a-frags, held in registers for the whole kv loop; scale folded in
    // once via packed fp16 multiply (replaces 64 FMULs per kv-tile).
    uint32_t qf[4][4];
    {
        const __half  sc_h  = __float2half_rn(0.125f * 1.4426950408889634f);
        const __half2 sc_h2 = __half2half2(sc_h);
        const uint32_t sc2  = *(const uint32_t*)&sc_h2;
        #pragma unroll
        for (int ks = 0; ks < 4; ks++) {
            const int row = warp * 16 + (lane & 15);
            const int ch  = ks * 2 + (lane >> 4);
            ldsm4(qf[ks], sbase + Q_OFF + SWZ128(row * 128 + ch * 16));
            #pragma unroll
            for (int q4 = 0; q4 < 4; q4++)
                qf[ks][q4] = mul_h2(qf[ks][q4], sc2);
        }
    }

    float o[8][4];
    #pragma unroll
    for (int i = 0; i < 8; i++)
        #pragma unroll
        for (int jj = 0; jj < 4; jj++) o[i][jj] = 0.f;
    float m0 = -INFINITY, m1 = -INFINITY, l0 = 0.f, l1 = 0.f;

    const int jend = (qt * 64 + 63) >> 7;   // last kv-128 tile needed
    for (int j = 0; j <= jend; j++) {
        const int cur = j & 1;
        if (j < jend) { load_kv(j + 1, cur ^ 1); CP_COMMIT; }

        const uint32_t kS = sbase + K_OFF + cur * KV_STG;
        const uint32_t vS = sbase + V_OFF + cur * KV_STG;

        // S = (Q*scale) @ K^T   (16 q-rows x 128 kv per warp; base-2 logits)
        float s[16][4];
        #pragma unroll
        for (int nt = 0; nt < 16; nt++)
            #pragma unroll
            for (int k4 = 0; k4 < 4; k4++) s[nt][k4] = 0.f;

        #pragma unroll
        for (int ks = 0; ks < 4; ks++) {
            uint32_t bf[16][2];
            #pragma unroll
            for (int pr = 0; pr < 8; pr++) {
                const int row = pr * 16 + (lane & 7) + ((lane >> 4) << 3);
                const int ch  = ks * 2 + ((lane >> 3) & 1);
                uint32_t rr[4];
                ldsm4(rr, kS + SWZ128(row * 128 + ch * 16));
                bf[pr * 2][0] = rr[0];     bf[pr * 2][1] = rr[1];
                bf[pr * 2 + 1][0] = rr[2]; bf[pr * 2 + 1][1] = rr[3];
            }
            #pragma unroll
            for (int nt = 0; nt < 16; nt++)
                mma_f16(s[nt], qf[ks], bf[nt]);
        }

        // causal mask (only the last tile can straddle the diagonal)
        if (j == jend) {
            const int rg0 = qt * 64 + warp * 16 + g;
            const int rg1 = rg0 + 8;
            #pragma unroll
            for (int nt = 0; nt < 16; nt++) {
                const int c0 = j * 128 + nt * 8 + 2 * tg;
                if (c0     > rg0) s[nt][0] = -1e30f;
                if (c0 + 1 > rg0) s[nt][1] = -1e30f;
                if (c0     > rg1) s[nt][2] = -1e30f;
                if (c0 + 1 > rg1) s[nt][3] = -1e30f;
            }
        }

        // online softmax, base-2 (row g -> s[.][0,1]; row g+8 -> s[.][2,3])
        float mt0 = -INFINITY, mt1 = -INFINITY;
        #pragma unroll
        for (int nt = 0; nt < 16; nt++) {
            mt0 = fmaxf(mt0, fmaxf(s[nt][0], s[nt][1]));
            mt1 = fmaxf(mt1, fmaxf(s[nt][2], s[nt][3]));
        }
        mt0 = fmaxf(mt0, __shfl_xor_sync(0xffffffffu, mt0, 1));
        mt0 = fmaxf(mt0, __shfl_xor_sync(0xffffffffu, mt0, 2));
        mt1 = fmaxf(mt1, __shfl_xor_sync(0xffffffffu, mt1, 1));
        mt1 = fmaxf(mt1, __shfl_xor_sync(0xffffffffu, mt1, 2));

        const float mn0 = fmaxf(m0, mt0), mn1 = fmaxf(m1, mt1);
        const float f0 = ex2f(m0 - mn0), f1 = ex2f(m1 - mn1);

        // exp + pack P directly into a-frags (c-frag layout == a-frag layout)
        uint32_t pf[8][4];
        float ls0 = 0.f, ls1 = 0.f;
        #pragma unroll
        for (int ks = 0; ks < 8; ks++) {
            const float pa0 = ex2f(s[2*ks][0] - mn0);
            const float pa1 = ex2f(s[2*ks][1] - mn0);
            const float pa2 = ex2f(s[2*ks][2] - mn1);
            const float pa3 = ex2f(s[2*ks][3] - mn1);
            const float pb0 = ex2f(s[2*ks+1][0] - mn0);
            const float pb1 = ex2f(s[2*ks+1][1] - mn0);
            const float pb2 = ex2f(s[2*ks+1][2] - mn1);
            const float pb3 = ex2f(s[2*ks+1][3] - mn1);
            ls0 += pa0 + pa1 + pb0 + pb1;
            ls1 += pa2 + pa3 + pb2 + pb3;
            pf[ks][0] = pack_h2(pa0, pa1);
            pf[ks][1] = pack_h2(pa2, pa3);
            pf[ks][2] = pack_h2(pb0, pb1);
            pf[ks][3] = pack_h2(pb2, pb3);
        }
        ls0 += __shfl_xor_sync(0xffffffffu, ls0, 1);
        ls0 += __shfl_xor_sync(0xffffffffu, ls0, 2);
        ls1 += __shfl_xor_sync(0xffffffffu, ls1, 1);
        ls1 += __shfl_xor_sync(0xffffffffu, ls1, 2);

        l0 = l0 * f0 + ls0;
        l1 = l1 * f1 + ls1;
        m0 = mn0; m1 = mn1;

        #pragma unroll
        for (int nt = 0; nt < 8; nt++) {
            o[nt][0] *= f0; o[nt][1] *= f0;
            o[nt][2] *= f1; o[nt][3] *= f1;
        }

        // O += P @ V   (P a-frags in registers; V b-frags via ldmatrix.trans)
        #pragma unroll
        for (int ks = 0; ks < 8; ks++) {
            uint32_t bf[8][2];
            #pragma unroll
            for (int pr = 0; pr < 4; pr++) {
                const int row = ks * 16 + (lane & 15);
                const int ch  = pr * 2 + (lane >> 4);
                uint32_t r0, r1, r2, r3;
                ldsm4t(r0, r1, r2, r3, vS + SWZ128(row * 128 + ch * 16));
                bf[pr * 2][0] = r0;     bf[pr * 2][1] = r1;
                bf[pr * 2 + 1][0] = r2; bf[pr * 2 + 1][1] = r3;
            }
            #pragma unroll
            for (int nt = 0; nt < 8; nt++)
                mma_f16(o[nt], pf[ks], bf[nt]);
        }

        if (j < jend) { CP_WAIT_0; __syncthreads(); }
    }

    // normalize + write y (half)
    const float i0 = 1.f / l0, i1 = 1.f / l1;
    const int r0 = b * T_ + qt * 64 + warp * 16 + g;
    #pragma unroll
    for (int nt = 0; nt < 8; nt++) {
        const int c = h * HD_ + nt * 8 + 2 * tg;
        *(__half2*)&y[(size_t)r0 * C_ + c] =
            __floats2half2_rn(o[nt][0] * i0, o[nt][1] * i0);
        *(__half2*)&y[(size_t)(r0 + 8) * C_ + c] =
            __floats2half2_rn(o[nt][2] * i1, o[nt][3] * i1);
    }
}

// ---------------------------------------------------------------------------
// Launch chain: convert -> qkv GEMM -> attention -> proj GEMM
// ---------------------------------------------------------------------------
extern "C" void kernel_launch(void* const* d_in, const int* in_sizes, int n_in,
                              void* d_out, int out_size)
{
    (void)in_sizes; (void)n_in; (void)out_size;
    const float* x      = (const float*)d_in[0];
    const float* w_attn = (const float*)d_in[1];
    const float* w_proj = (const float*)d_in[2];
    float* out = (float*)d_out;

    __half *qkv, *y, *xh, *wah, *wph;
    cudaGetSymbolAddress((void**)&qkv, g_qkv);
    cudaGetSymbolAddress((void**)&y,   g_y);
    cudaGetSymbolAddress((void**)&xh,  g_xh);
    cudaGetSymbolAddress((void**)&wah, g_wah);
    cudaGetSymbolAddress((void**)&wph, g_wph);

    cudaFuncSetAttribute(gemm_f16<true>,  cudaFuncAttributeMaxDynamicSharedMemorySize, GEMM_SMEM);
    cudaFuncSetAttribute(gemm_f16<false>, cudaFuncAttributeMaxDynamicSharedMemorySize, GEMM_SMEM);
    cudaFuncSetAttribute(attn_kernel,     cudaFuncAttributeMaxDynamicSharedMemorySize, ATT_SMEM);

    const int n4x = ROWS_ * C_ / 4;       // 1048576
    const int n4a = C_ * C3_ / 4;         // 786432
    const int n4p = C_ * C_ / 4;          // 262144
    const int n4  = n4x + n4a + n4p;
    convert_all_kernel<<<(n4 + 255) / 256, 256>>>(
        (const float4*)x, (uint2*)xh,
        (const float4*)w_attn, (uint2*)wah,
        (const float4*)w_proj, (uint2*)wph,
        n4x, n4a, n4p);

    gemm_f16<true><<<dim3(C3_ / BN, ROWS_ / BM), 128, GEMM_SMEM>>>(xh, wah, qkv, ROWS_, C3_, C_);
    attn_kernel<<<dim3(T_ / 64, B_ * NH_), 128, ATT_SMEM>>>(qkv, y);
    gemm_f16<false><<<dim3(C_ / BN, ROWS_ / BM), 128, GEMM_SMEM>>>(y, wph, out, ROWS_, C_, C_);
}